// round 17
// baseline (speedup 1.0000x reference)
#include <cuda_runtime.h>
#include <math.h>
#include <stdint.h>

#define N0  65536     // total nodes
#define E0  524288    // total edges
#define NB  32        // graphs
#define FHC 256       // feature width (H*C)

// ---------------- static device scratch ----------------
__device__ float g_h0[(size_t)N0 * FHC];
__device__ float g_h1[(size_t)N0 * FHC];
__device__ float g_ho[(size_t)N0 * FHC];
__device__ float g_hp[(size_t)(N0 / 2) * FHC];
__device__ float g_wsp[6 * 65536];   // presplit weights: lin0 hi/lo, gat0 hi/lo, gat1 hi/lo
__device__ float g_as[N0 * 4], g_ad[N0 * 4];
__device__ float g_sc[N0];
__device__ float g_graw[N0];         // raw gate dot <ho_row, gate_w>
__device__ float g_th[N0 / 2];
__device__ int g_s0[E0], g_d0[E0], g_s1[E0], g_d1[E0];
__device__ unsigned char g_v1[E0];
__device__ int g_deg[N0], g_off[N0 + 1], g_cur[N0], g_csr[E0];
__device__ int g_bs[64];             // lookback flags (value = chunk total + 1)
__device__ int g_pm[N0 / 2], g_nid[N0];

static inline int divup(int a, int b) { return (a + b - 1) / b; }

__device__ __forceinline__ float lrelu(float z) { return z > 0.f ? z : 0.2f * z; }

// ---------------- tf32 helpers ----------------
__device__ __forceinline__ void tf32split(float x, uint32_t& hi, uint32_t& lo) {
    asm("cvt.rna.tf32.f32 %0, %1;" : "=r"(hi) : "f"(x));
    float r = x - __uint_as_float(hi);
    asm("cvt.rna.tf32.f32 %0, %1;" : "=r"(lo) : "f"(r));
}

#define MMA_TF32(d, a, b0, b1)                                                   \
    asm volatile(                                                                \
        "mma.sync.aligned.m16n8k8.row.col.f32.tf32.tf32.f32 "                    \
        "{%0,%1,%2,%3},{%4,%5,%6,%7},{%8,%9},{%0,%1,%2,%3};"                     \
        : "+f"(d[0]), "+f"(d[1]), "+f"(d[2]), "+f"(d[3])                         \
        : "r"(a[0]), "r"(a[1]), "r"(a[2]), "r"(a[3]), "r"(b0), "r"(b1))

__device__ __forceinline__ void cpa16(uint32_t dst, const void* src) {
    asm volatile("cp.async.cg.shared.global [%0], [%1], 16;" :: "r"(dst), "l"(src));
}
__device__ __forceinline__ void cpa4(uint32_t dst, const void* src) {
    asm volatile("cp.async.ca.shared.global [%0], [%1], 4;" :: "r"(dst), "l"(src));
}

// ---------------- kernels ----------------

// split all three weight matrices into tf32 hi/lo (one pass)
__global__ void k_wsplit(const float* __restrict__ w0, const float* __restrict__ w1,
                         const float* __restrict__ w2, float* __restrict__ wsp) {
    int i = blockIdx.x * blockDim.x + threadIdx.x;
    const float* src;
    float *hi, *lo;
    int li;
    if (i < 32768)        { src = w0; li = i;          hi = wsp;            lo = wsp + 65536; }
    else if (i < 98304)   { src = w1; li = i - 32768;  hi = wsp + 131072;   lo = wsp + 196608; }
    else if (i < 163840)  { src = w2; li = i - 98304;  hi = wsp + 262144;   lo = wsp + 327680; }
    else return;
    uint32_t h, l;
    tf32split(src[li], h, l);
    hi[li] = __uint_as_float(h);
    lo[li] = __uint_as_float(l);
}

// decode edges + count in-degrees; int64-vs-int32 detection fused per block
__global__ void k_edges_deg(const void* __restrict__ ei, int* __restrict__ s,
                            int* __restrict__ d, int* __restrict__ deg, int E) {
    __shared__ int s64;
    if (threadIdx.x == 0) {
        const int* w = (const int*)ei;
        int nz = 0;
        for (int i = 1; i < 128; i += 2) nz |= (w[i] != 0);
        s64 = nz ? 0 : 1;
    }
    __syncthreads();
    int i = blockIdx.x * blockDim.x + threadIdx.x;
    if (i >= E) return;
    int sv, dv;
    if (s64) {
        const long long* p = (const long long*)ei;
        sv = (int)p[i];
        dv = (int)p[E + i];
    } else {
        const int* p = (const int*)ei;
        sv = p[i];
        dv = p[E + i];
    }
    s[i] = sv; d[i] = dv;
    atomicAdd(&deg[dv], 1);
}

// Tensor-core GEMM, 3xTF32. B (weights) presplit in global hi/lo; A split
// in registers. Double-buffered cp.async. Block tile 128x128, BK=32,
// 256 threads (8 warps, warp tile 32x64), 2 CTAs/SM; grid (N/128, M/128).
#define AP 36
#define BP 136
#define ABUF (128 * AP)
#define BBUF (32 * BP)
#define SBUF (ABUF + 2 * BBUF)
#define SMEM_GEMM (2 * SBUF * 4)
__global__ void __launch_bounds__(256, 2)
k_gemm_tc(const float* __restrict__ A, const float* __restrict__ Bh,
          const float* __restrict__ Bl,
          const float* __restrict__ bias, float* __restrict__ Cm,
          int M, int K, int N, int act, int Kld,
          const float* __restrict__ a1col, const float* __restrict__ b1row,
          const float* __restrict__ aS, const float* __restrict__ aD,
          float* __restrict__ as_, float* __restrict__ ad_) {
    extern __shared__ float smg[];
    int t = threadIdx.x;
    int lane = t & 31, w = t >> 5;
    int g = lane >> 2, tig = lane & 3;
    int wm = w & 3, wn = w >> 2;
    int row0 = blockIdx.y * 128;
    int col0 = blockIdx.x * 128;
    int nk = K >> 5;
    bool al16 = (Kld & 3) == 0;

    float acc[2][8][4];
#pragma unroll
    for (int i = 0; i < 2; i++)
#pragma unroll
        for (int j = 0; j < 8; j++)
#pragma unroll
            for (int q = 0; q < 4; q++) acc[i][j][q] = 0.f;

    auto copy_tile = [&](int ti, int bf) {
        float* As  = smg + bf * SBUF;
        float* Bsh = As + ABUF;
        float* Bsl = Bsh + BBUF;
#pragma unroll
        for (int it = 0; it < 4; it++) {
            int lin = t + 256 * it;
            int r = lin >> 3, c4 = (lin & 7) * 4;
            const float* src = &A[(size_t)(row0 + r) * Kld + ti * 32 + c4];
            uint32_t dst = (uint32_t)__cvta_generic_to_shared(&As[r * AP + c4]);
            if (al16) {
                cpa16(dst, src);
            } else {
#pragma unroll
                for (int j = 0; j < 4; j++) cpa4(dst + j * 4, src + j);
            }
        }
#pragma unroll
        for (int it = 0; it < 4; it++) {
            int lin = t + 256 * it;
            int kk = lin >> 5, c4 = (lin & 31) * 4;
            size_t gsrc = (size_t)(ti * 32 + kk) * N + col0 + c4;
            cpa16((uint32_t)__cvta_generic_to_shared(&Bsh[kk * BP + c4]), &Bh[gsrc]);
            cpa16((uint32_t)__cvta_generic_to_shared(&Bsl[kk * BP + c4]), &Bl[gsrc]);
        }
    };

    copy_tile(0, 0);
    asm volatile("cp.async.commit_group;");

    for (int ti = 0; ti < nk; ti++) {
        if (ti + 1 < nk) {
            copy_tile(ti + 1, (ti + 1) & 1);
            asm volatile("cp.async.commit_group;");
            asm volatile("cp.async.wait_group 1;");
        } else {
            asm volatile("cp.async.wait_group 0;");
        }
        __syncthreads();
        const float* As  = smg + (ti & 1) * SBUF;
        const float* Bsh = As + ABUF;
        const float* Bsl = Bsh + BBUF;
#pragma unroll
        for (int ks = 0; ks < 4; ks++) {
            int k8 = ks * 8;
            uint32_t ah[2][4], al[2][4];
#pragma unroll
            for (int mt = 0; mt < 2; mt++) {
                int bm = wm * 32 + mt * 16 + g;
                tf32split(As[bm * AP + k8 + tig],           ah[mt][0], al[mt][0]);
                tf32split(As[(bm + 8) * AP + k8 + tig],     ah[mt][1], al[mt][1]);
                tf32split(As[bm * AP + k8 + tig + 4],       ah[mt][2], al[mt][2]);
                tf32split(As[(bm + 8) * AP + k8 + tig + 4], ah[mt][3], al[mt][3]);
            }
#pragma unroll
            for (int nt = 0; nt < 8; nt++) {
                int bn = wn * 64 + nt * 8 + g;
                uint32_t b0h = __float_as_uint(Bsh[(k8 + tig) * BP + bn]);
                uint32_t b1h = __float_as_uint(Bsh[(k8 + tig + 4) * BP + bn]);
                uint32_t b0l = __float_as_uint(Bsl[(k8 + tig) * BP + bn]);
                uint32_t b1l = __float_as_uint(Bsl[(k8 + tig + 4) * BP + bn]);
#pragma unroll
                for (int mt = 0; mt < 2; mt++) {
                    MMA_TF32(acc[mt][nt], ah[mt], b0h, b1h);
                    MMA_TF32(acc[mt][nt], ah[mt], b0l, b1l);
                    MMA_TF32(acc[mt][nt], al[mt], b0h, b1h);
                }
            }
        }
        __syncthreads();
    }

#pragma unroll
    for (int mt = 0; mt < 2; mt++) {
        int r = row0 + wm * 32 + mt * 16 + g;
        float ar0 = a1col ? a1col[(size_t)r * Kld] : 0.f;
        float ar8 = a1col ? a1col[(size_t)(r + 8) * Kld] : 0.f;
#pragma unroll
        for (int nt = 0; nt < 8; nt++) {
            int cc = col0 + wn * 64 + nt * 8 + tig * 2;
            float bb0 = a1col ? b1row[cc] : 0.f, bb1 = a1col ? b1row[cc + 1] : 0.f;
            float b0 = bias ? bias[cc] : 0.f, b1 = bias ? bias[cc + 1] : 0.f;
            float v0 = acc[mt][nt][0] + ar0 * bb0 + b0;
            float v1 = acc[mt][nt][1] + ar0 * bb1 + b1;
            float v2 = acc[mt][nt][2] + ar8 * bb0 + b0;
            float v3 = acc[mt][nt][3] + ar8 * bb1 + b1;
            if (act) {
                v0 = fmaxf(v0, 0.f); v1 = fmaxf(v1, 0.f);
                v2 = fmaxf(v2, 0.f); v3 = fmaxf(v3, 0.f);
            }
            float2 p0 = {v0, v1}, p1 = {v2, v3};
            *(float2*)&Cm[(size_t)r * N + cc] = p0;
            *(float2*)&Cm[(size_t)(r + 8) * N + cc] = p1;
        }
    }

    // fused attention epilogue: warp wn's 64 cols = head (blockIdx.x*2 + wn)
    if (aS) {
        int head = blockIdx.x * 2 + wn;
        const float* ws = aS + head * 64;
        const float* wd = aD + head * 64;
#pragma unroll
        for (int mt = 0; mt < 2; mt++) {
            float s0 = 0.f, d0 = 0.f, s1 = 0.f, d1 = 0.f;
#pragma unroll
            for (int nt = 0; nt < 8; nt++) {
                int c = nt * 8 + tig * 2;
                float w0 = ws[c], w1 = ws[c + 1];
                float u0 = wd[c], u1 = wd[c + 1];
                s0 = fmaf(acc[mt][nt][0], w0, fmaf(acc[mt][nt][1], w1, s0));
                d0 = fmaf(acc[mt][nt][0], u0, fmaf(acc[mt][nt][1], u1, d0));
                s1 = fmaf(acc[mt][nt][2], w0, fmaf(acc[mt][nt][3], w1, s1));
                d1 = fmaf(acc[mt][nt][2], u0, fmaf(acc[mt][nt][3], u1, d1));
            }
#pragma unroll
            for (int o = 1; o <= 2; o <<= 1) {
                s0 += __shfl_xor_sync(0xffffffffu, s0, o);
                d0 += __shfl_xor_sync(0xffffffffu, d0, o);
                s1 += __shfl_xor_sync(0xffffffffu, s1, o);
                d1 += __shfl_xor_sync(0xffffffffu, d1, o);
            }
            if (tig == 0) {
                int r = row0 + wm * 32 + mt * 16 + g;
                as_[r * 4 + head] = s0; ad_[r * 4 + head] = d0;
                as_[(r + 8) * 4 + head] = s1; ad_[(r + 8) * 4 + head] = d1;
            }
        }
    }
}

// single-pass exclusive scan with decoupled lookback; nb = gridDim.x <= 64.
__global__ void __launch_bounds__(1024) k_scanF(const int* __restrict__ in,
                                                int* __restrict__ off,
                                                int* __restrict__ cur,
                                                int* __restrict__ bflag, int n) {
    __shared__ int sm[1024];
    __shared__ int spre;
    int t = threadIdx.x, b = blockIdx.x;
    int i = b * 1024 + t;
    int v = (i < n) ? in[i] : 0;
    sm[t] = v;
    __syncthreads();
    for (int o = 1; o < 1024; o <<= 1) {
        int u = (t >= o) ? sm[t - o] : 0;
        __syncthreads();
        sm[t] += u;
        __syncthreads();
    }
    if (t == 0) { spre = 0; atomicExch(&bflag[b], sm[1023] + 1); }
    __syncthreads();
    if (t < b) {
        int f;
        do { f = atomicAdd(&bflag[t], 0); } while (f == 0);
        atomicAdd(&spre, f - 1);
    }
    __syncthreads();
    int exc = spre + sm[t] - v;
    if (i < n) { off[i] = exc; cur[i] = exc; }
    if (b == gridDim.x - 1 && t == 1023) off[n] = spre + sm[1023];
}

__global__ void k_escatter(const int* __restrict__ s, const int* __restrict__ d,
                           const unsigned char* __restrict__ val, int* __restrict__ cur,
                           int* __restrict__ csr, int E) {
    int e = blockIdx.x * blockDim.x + threadIdx.x;
    if (e >= E) return;
    if (val && !val[e]) return;
    int p = atomicAdd(&cur[d[e]], 1);
    csr[p] = s[e];
}

// Fused GAT aggregation + topk score + raw gate dot: warp per dst node,
// no-shift softmax, predicated 4-batches for MLP=4 through the tail.
__global__ void k_gather(const float* __restrict__ h1, const int* __restrict__ off,
                         const int* __restrict__ csr,
                         const float* __restrict__ as_, const float* __restrict__ ad_,
                         const float* __restrict__ bias, const float* __restrict__ pw,
                         const float* __restrict__ gw,
                         float* __restrict__ out, float* __restrict__ sc,
                         float* __restrict__ graw, int n) {
    int wp = (blockIdx.x * blockDim.x + threadIdx.x) >> 5;
    if (wp >= n) return;
    int lane = threadIdx.x & 31;
    int head = lane >> 3;
    int d = wp;
    float adh = ad_[d * 4 + head];
    float w0s = expf(lrelu(as_[d * 4 + head] + adh));   // self loop
    float den = w0s;
    float acc[8];
    {
        const float4* p = (const float4*)(h1 + (size_t)d * FHC + lane * 8);
        float4 x0 = p[0], x1 = p[1];
        acc[0] = w0s * x0.x; acc[1] = w0s * x0.y; acc[2] = w0s * x0.z; acc[3] = w0s * x0.w;
        acc[4] = w0s * x1.x; acc[5] = w0s * x1.y; acc[6] = w0s * x1.z; acc[7] = w0s * x1.w;
    }
    int e0 = off[d], e1 = off[d + 1];
    for (int e = e0; e < e1; e += 4) {
        int sv[4];
        float wgt[4];
        float4 f0[4], f1[4];
#pragma unroll
        for (int i = 0; i < 4; i++) {
            bool ok = (e + i < e1);
            sv[i] = ok ? csr[e + i] : d;
            wgt[i] = ok ? 1.f : 0.f;
        }
#pragma unroll
        for (int i = 0; i < 4; i++) {
            wgt[i] *= expf(lrelu(as_[sv[i] * 4 + head] + adh));
            const float4* p = (const float4*)(h1 + (size_t)sv[i] * FHC + lane * 8);
            f0[i] = p[0]; f1[i] = p[1];
        }
#pragma unroll
        for (int i = 0; i < 4; i++) {
            den += wgt[i];
            acc[0] = fmaf(wgt[i], f0[i].x, acc[0]);
            acc[1] = fmaf(wgt[i], f0[i].y, acc[1]);
            acc[2] = fmaf(wgt[i], f0[i].z, acc[2]);
            acc[3] = fmaf(wgt[i], f0[i].w, acc[3]);
            acc[4] = fmaf(wgt[i], f1[i].x, acc[4]);
            acc[5] = fmaf(wgt[i], f1[i].y, acc[5]);
            acc[6] = fmaf(wgt[i], f1[i].z, acc[6]);
            acc[7] = fmaf(wgt[i], f1[i].w, acc[7]);
        }
    }
    float inv = 1.f / (den + 1e-16f);
    int cb = lane * 8;
    float4 o0, o1;
    float v;
    v = acc[0] * inv + bias[cb + 0]; o0.x = v > 0.f ? v : expm1f(v);
    v = acc[1] * inv + bias[cb + 1]; o0.y = v > 0.f ? v : expm1f(v);
    v = acc[2] * inv + bias[cb + 2]; o0.z = v > 0.f ? v : expm1f(v);
    v = acc[3] * inv + bias[cb + 3]; o0.w = v > 0.f ? v : expm1f(v);
    v = acc[4] * inv + bias[cb + 4]; o1.x = v > 0.f ? v : expm1f(v);
    v = acc[5] * inv + bias[cb + 5]; o1.y = v > 0.f ? v : expm1f(v);
    v = acc[6] * inv + bias[cb + 6]; o1.z = v > 0.f ? v : expm1f(v);
    v = acc[7] * inv + bias[cb + 7]; o1.w = v > 0.f ? v : expm1f(v);
    float4* po = (float4*)(out + (size_t)d * FHC + cb);
    __stcs(po, o0);
    __stcs(po + 1, o1);
    const float4* pwp = (const float4*)(pw + cb);
    const float4* gwp = (const float4*)(gw + cb);
    float4 w0 = pwp[0], w1 = pwp[1];
    float4 q0 = gwp[0], q1 = gwp[1];
    float sp = o0.x * w0.x + o0.y * w0.y + o0.z * w0.z + o0.w * w0.w +
               o1.x * w1.x + o1.y * w1.y + o1.z * w1.z + o1.w * w1.w;
    float n2 = w0.x * w0.x + w0.y * w0.y + w0.z * w0.z + w0.w * w0.w +
               w1.x * w1.x + w1.y * w1.y + w1.z * w1.z + w1.w * w1.w;
    float gg = o0.x * q0.x + o0.y * q0.y + o0.z * q0.z + o0.w * q0.w +
               o1.x * q1.x + o1.y * q1.y + o1.z * q1.z + o1.w * q1.w;
#pragma unroll
    for (int o = 16; o; o >>= 1) {
        sp += __shfl_xor_sync(0xffffffffu, sp, o);
        n2 += __shfl_xor_sync(0xffffffffu, n2, o);
        gg += __shfl_xor_sync(0xffffffffu, gg, o);
    }
    if (!lane) {
        sc[d] = sp / (sqrtf(n2) + 1e-16f);
        graw[d] = gg;
    }
}

// exact top-k per graph via 4-pass radix select on sortable uint keys.
__global__ void __launch_bounds__(1024) k_topk(const float* __restrict__ score, int n_in,
                                               int k, int* __restrict__ perm,
                                               float* __restrict__ tanhv,
                                               int* __restrict__ newid) {
    __shared__ unsigned su[2048];
    __shared__ int hist[256];
    __shared__ int sscan[1024];
    __shared__ unsigned s_thr;
    __shared__ int s_kk;
    __shared__ int s_totgt;
    int b = blockIdx.x, t = threadIdx.x;
    const float* s = score + b * n_in;
    int per = n_in >> 10;  // 1 or 2
    for (int i = t; i < n_in; i += 1024) {
        unsigned u = __float_as_uint(s[i]);
        su[i] = (u & 0x80000000u) ? ~u : (u | 0x80000000u);
    }
    __syncthreads();
    unsigned prefix = 0u;
    int kk = k;
    for (int pass = 0; pass < 4; pass++) {
        int shift = 24 - 8 * pass;
        unsigned pmask = pass ? (0xFFFFFFFFu << (shift + 8)) : 0u;
        if (t < 256) hist[t] = 0;
        __syncthreads();
        for (int i = t; i < n_in; i += 1024) {
            unsigned u = su[i];
            if ((u & pmask) == (prefix & pmask))
                atomicAdd(&hist[(u >> shift) & 0xFFu], 1);
        }
        __syncthreads();
        if (t == 0) {
            int acc = 0, d = 255;
            for (; d > 0; d--) {
                int c = hist[d];
                if (acc + c >= kk) break;
                acc += c;
            }
            s_thr = (prefix & pmask) | ((unsigned)d << shift);
            s_kk = kk - acc;
        }
        __syncthreads();
        prefix = s_thr;
        kk = s_kk;
        __syncthreads();
    }
    unsigned T = prefix;
    int isgt[2] = {0, 0}, iseq[2] = {0, 0};
    int keepc = 0, eqc = 0;
    for (int q = 0; q < 2; q++) {
        if (q < per) {
            unsigned u = su[t * per + q];
            isgt[q] = (u > T);
            iseq[q] = (u == T);
            keepc += isgt[q];
            eqc += iseq[q];
        }
    }
    sscan[t] = (eqc << 16) | keepc;
    __syncthreads();
    for (int o = 1; o < 1024; o <<= 1) {
        int u = (t >= o) ? sscan[t - o] : 0;
        __syncthreads();
        sscan[t] += u;
        __syncthreads();
    }
    int packed_exc = sscan[t] - ((eqc << 16) | keepc);
    int gtpos = packed_exc & 0xFFFF;
    int eqrank = packed_exc >> 16;
    if (t == 1023) s_totgt = sscan[1023] & 0xFFFF;
    __syncthreads();
    int totgt = s_totgt;
    for (int q = 0; q < per; q++) {
        int idx = t * per + q;
        int old = b * n_in + idx;
        bool kept = false;
        int pos = 0;
        if (isgt[q]) {
            kept = true; pos = gtpos; gtpos++;
        } else if (iseq[q]) {
            kept = (eqrank < kk); pos = totgt + eqrank; eqrank++;
        }
        if (kept) {
            int np = b * k + pos;
            perm[np] = old;
            tanhv[np] = tanhf(s[idx]);
            newid[old] = np;
        } else {
            newid[old] = -1;
        }
    }
}

// warp per pooled node: hp = h[perm]*tanh (pure copy; gates handled via graw)
__global__ void k_poolfeat(const float* __restrict__ h, const int* __restrict__ pm,
                           const float* __restrict__ th, float* __restrict__ hp, int m) {
    int wp = (blockIdx.x * blockDim.x + threadIdx.x) >> 5;
    if (wp >= m) return;
    int lane = threadIdx.x & 31;
    int srcn = pm[wp];
    float tv = th[wp];
    int cb = lane * 8;
    const float4* p = (const float4*)(h + (size_t)srcn * FHC + cb);
    float4 a = p[0], b = p[1];
    a.x *= tv; a.y *= tv; a.z *= tv; a.w *= tv;
    b.x *= tv; b.y *= tv; b.z *= tv; b.w *= tv;
    float4* po = (float4*)(hp + (size_t)wp * FHC + cb);
    po[0] = a; po[1] = b;
}

// remap edges to pooled ids + count pooled in-degrees (fused)
__global__ void k_remap_deg(const int* __restrict__ si, const int* __restrict__ di,
                            const int* __restrict__ nid, int* __restrict__ so,
                            int* __restrict__ dq, unsigned char* __restrict__ vo,
                            int* __restrict__ deg, int E) {
    int e = blockIdx.x * blockDim.x + threadIdx.x;
    if (e >= E) return;
    int ns = nid[si[e]], nd = nid[di[e]];
    bool v = (ns >= 0) && (nd >= 0);
    so[e] = v ? ns : 0;
    dq[e] = v ? nd : 0;
    vo[e] = v ? 1 : 0;
    if (v) atomicAdd(&deg[nd], 1);
}

// attentional pooling reading pooled rows via perm indirection.
// gate_i = th[i]*graw[perm[i]] + gb (exact factorization of <h_row*th, gw>+gb).
__global__ void k_attpool2(const float* __restrict__ ho, const int* __restrict__ perm,
                           const float* __restrict__ th, const float* __restrict__ graw,
                           const float* __restrict__ gb, float* __restrict__ out,
                           int npg) {
    __shared__ float red[256];
    __shared__ float gbuf[1024];
    int b = blockIdx.y, t = threadIdx.x;
    float gb0 = gb[0];
    for (int i = t; i < npg; i += 256)
        gbuf[i] = th[b * npg + i] * graw[perm[b * npg + i]] + gb0;
    __syncthreads();
    float mxv = -1e30f;
    for (int i = t; i < npg; i += 256) mxv = fmaxf(mxv, gbuf[i]);
    red[t] = mxv;
    __syncthreads();
    for (int o = 128; o; o >>= 1) { if (t < o) red[t] = fmaxf(red[t], red[t + o]); __syncthreads(); }
    float m = red[0];
    __syncthreads();
    float sum = 0.f;
    for (int i = t; i < npg; i += 256) sum += expf(gbuf[i] - m);
    red[t] = sum;
    __syncthreads();
    for (int o = 128; o; o >>= 1) { if (t < o) red[t] += red[t + o]; __syncthreads(); }
    float inv = 1.f / red[0];
    int chunk = npg >> 3;
    int i0 = blockIdx.x * chunk;
    float a = 0.f;
    for (int i = 0; i < chunk; i++) {
        int pi = b * npg + i0 + i;
        float wv = expf(gbuf[i0 + i] - m) * th[pi];
        a = fmaf(wv, ho[(size_t)perm[pi] * FHC + t], a);
    }
    atomicAdd(&out[b * FHC + t], a * inv);
}

// ---------------- host side ----------------

extern "C" void kernel_launch(void* const* d_in, const int* in_sizes, int n_in,
                              void* d_out, int out_size) {
    const float* x        = (const float*)d_in[0];
    const void*  ei       = d_in[1];
    const float* lin0_w   = (const float*)d_in[2];
    const float* lin0_b   = (const float*)d_in[3];
    const float* gat0_W   = (const float*)d_in[4];
    const float* gat0_as  = (const float*)d_in[5];
    const float* gat0_ad  = (const float*)d_in[6];
    const float* gat0_b   = (const float*)d_in[7];
    const float* pool0_w  = (const float*)d_in[8];
    const float* gat1_W   = (const float*)d_in[9];
    const float* gat1_as  = (const float*)d_in[10];
    const float* gat1_ad  = (const float*)d_in[11];
    const float* gat1_b   = (const float*)d_in[12];
    const float* pool1_w  = (const float*)d_in[13];
    const float* gate_w   = (const float*)d_in[14];
    const float* gate_b   = (const float*)d_in[15];
    float* out = (float*)d_out;

    float *h0, *h1, *ho, *hp, *wsp, *as_, *ad_, *sc, *graw, *th;
    int *s0, *d0, *s1, *d1, *deg, *off, *cur, *csr, *pm, *nid, *bs;
    unsigned char* v1;
    cudaGetSymbolAddress((void**)&h0, g_h0);
    cudaGetSymbolAddress((void**)&h1, g_h1);
    cudaGetSymbolAddress((void**)&ho, g_ho);
    cudaGetSymbolAddress((void**)&hp, g_hp);
    cudaGetSymbolAddress((void**)&wsp, g_wsp);
    cudaGetSymbolAddress((void**)&as_, g_as);
    cudaGetSymbolAddress((void**)&ad_, g_ad);
    cudaGetSymbolAddress((void**)&sc, g_sc);
    cudaGetSymbolAddress((void**)&graw, g_graw);
    cudaGetSymbolAddress((void**)&th, g_th);
    cudaGetSymbolAddress((void**)&s0, g_s0);
    cudaGetSymbolAddress((void**)&d0, g_d0);
    cudaGetSymbolAddress((void**)&s1, g_s1);
    cudaGetSymbolAddress((void**)&d1, g_d1);
    cudaGetSymbolAddress((void**)&deg, g_deg);
    cudaGetSymbolAddress((void**)&off, g_off);
    cudaGetSymbolAddress((void**)&cur, g_cur);
    cudaGetSymbolAddress((void**)&csr, g_csr);
    cudaGetSymbolAddress((void**)&pm, g_pm);
    cudaGetSymbolAddress((void**)&nid, g_nid);
    cudaGetSymbolAddress((void**)&bs, g_bs);
    cudaGetSymbolAddress((void**)&v1, g_v1);

    cudaFuncSetAttribute(k_gemm_tc, cudaFuncAttributeMaxDynamicSharedMemorySize,
                         SMEM_GEMM);

    static cudaStream_t s2 = nullptr;
    static cudaEvent_t evF0, evS0, evT0, evS1, evA0;
    if (!s2) {
        cudaStreamCreateWithFlags(&s2, cudaStreamNonBlocking);
        cudaEventCreateWithFlags(&evF0, cudaEventDisableTiming);
        cudaEventCreateWithFlags(&evS0, cudaEventDisableTiming);
        cudaEventCreateWithFlags(&evT0, cudaEventDisableTiming);
        cudaEventCreateWithFlags(&evS1, cudaEventDisableTiming);
        cudaEventCreateWithFlags(&evA0, cudaEventDisableTiming);
    }

    const int EB = divup(E0, 256);

    // fork side stream immediately (CSR0 build depends only on inputs)
    cudaEventRecord(evF0, 0);
    cudaStreamWaitEvent(s2, evF0, 0);
    cudaMemsetAsync(deg, 0, (size_t)N0 * sizeof(int), s2);
    cudaMemsetAsync(bs, 0, 64 * sizeof(int), s2);
    k_edges_deg<<<EB, 256, 0, s2>>>(ei, s0, d0, deg, E0);
    k_scanF<<<N0 / 1024, 1024, 0, s2>>>(deg, off, cur, bs, N0);
    k_escatter<<<EB, 256, 0, s2>>>(s0, d0, nullptr, cur, csr, E0);
    cudaEventRecord(evS0, s2);

    // ---- main: zero out, presplit weights, then the two big GEMMs ----
    cudaMemsetAsync(out, 0, (size_t)NB * FHC * sizeof(float), 0);
    k_wsplit<<<divup(163840, 256), 256>>>(lin0_w, gat0_W, gat1_W, wsp);
    k_gemm_tc<<<dim3(2, N0 / 128), 256, SMEM_GEMM>>>(
        x, wsp, wsp + 65536, lin0_b, h0, N0, 128, 256, 1, 129,
        x + 128, lin0_w + 128 * 256, nullptr, nullptr, nullptr, nullptr);
    k_gemm_tc<<<dim3(2, N0 / 128), 256, SMEM_GEMM>>>(
        h0, wsp + 131072, wsp + 196608, nullptr, h1, N0, 256, 256, 0, 256,
        nullptr, nullptr, gat0_as, gat0_ad, as_, ad_);

    // join: gather0 needs CSR + h1/as_/ad_
    cudaStreamWaitEvent(0, evS0, 0);
    k_gather<<<divup(N0, 8), 256>>>(h1, off, csr, as_, ad_, gat0_b, pool0_w, gate_w,
                                    ho, sc, graw, N0);

    // TopK pool 0 (radix select)
    k_topk<<<NB, 1024>>>(sc, 2048, 1024, pm, th, nid);
    cudaEventRecord(evT0, 0);
    k_poolfeat<<<divup((N0 / 2) * 32, 256), 256>>>(ho, pm, th, hp, N0 / 2);

    // side: CSR build for GAT1 (needs nid), then attpool0 (reads ho/graw of GAT0)
    cudaStreamWaitEvent(s2, evT0, 0);
    cudaMemsetAsync(deg, 0, (size_t)(N0 / 2) * sizeof(int), s2);
    cudaMemsetAsync(bs, 0, 64 * sizeof(int), s2);
    k_remap_deg<<<EB, 256, 0, s2>>>(s0, d0, nid, s1, d1, v1, deg, E0);
    k_scanF<<<(N0 / 2) / 1024, 1024, 0, s2>>>(deg, off, cur, bs, N0 / 2);
    k_escatter<<<EB, 256, 0, s2>>>(s1, d1, v1, cur, csr, E0);
    cudaEventRecord(evS1, s2);
    k_attpool2<<<dim3(8, NB), 256, 0, s2>>>(ho, pm, th, graw, gate_b, out, 1024);
    cudaEventRecord(evA0, s2);

    // ---- main: GAT1 GEMM (writes h1 only; safe to overlap attpool0) ----
    k_gemm_tc<<<dim3(2, (N0 / 2) / 128), 256, SMEM_GEMM>>>(
        hp, wsp + 262144, wsp + 327680, nullptr, h1, N0 / 2, 256, 256, 0, 256,
        nullptr, nullptr, gat1_as, gat1_ad, as_, ad_);
    // gather1 OVERWRITES ho/graw -> must wait for CSR1 (evS1) AND attpool0 (evA0)
    cudaStreamWaitEvent(0, evS1, 0);
    cudaStreamWaitEvent(0, evA0, 0);
    k_gather<<<divup(N0 / 2, 8), 256>>>(h1, off, csr, as_, ad_, gat1_b, pool1_w, gate_w,
                                        ho, sc, graw, N0 / 2);

    // TopK pool 1, then attpool1 directly via perm indirection (no poolfeat1)
    k_topk<<<NB, 1024>>>(sc, 1024, 512, pm, th, nid);
    k_attpool2<<<dim3(8, NB), 256>>>(ho, pm, th, graw, gate_b, out, 512);
}